// round 9
// baseline (speedup 1.0000x reference)
#include <cuda_runtime.h>
#include <cstdint>

#define RELS 3
#define NMAX 50000
#define HD   256      // H = HF*AH
#define KIN  128      // in_feats

// ---------------- scratch (static device globals; no allocation) ----------------
__device__ float g_hw   [(size_t)RELS * NMAX * HD];   // 153.6 MB
__device__ float g_num  [(size_t)NMAX * RELS * HD];   // 153.6 MB (concat layout [N, 768])
__device__ float g_denom[(size_t)RELS * NMAX * 4];    // [r][n][head]
__device__ float g_rcp  [(size_t)NMAX * 12];          // [n][r*4+a] reciprocal of denom
__device__ float g_p1   [NMAX];
__device__ float g_p2   [NMAX];
__device__ float g_qs   [(size_t)RELS * NMAX * 4];
__device__ float g_qd   [(size_t)RELS * NMAX * 4];
__device__ float g_U    [32 * KIN];                   // folded projection vectors [col][k]
__device__ float g_Uc   [32];                         // folded constants per col

// ---------------- helpers ----------------
__device__ __forceinline__ void red_add_v4(float* p, float x, float y, float z, float w) {
    asm volatile("red.global.add.v4.f32 [%0], {%1, %2, %3, %4};"
                 :: "l"(p), "f"(x), "f"(y), "f"(z), "f"(w) : "memory");
}

// ---------------- zero-init kernels ----------------
__global__ void zero_num_kernel(size_t n4) {
    size_t i = (size_t)blockIdx.x * blockDim.x + threadIdx.x;
    if (i < n4) reinterpret_cast<float4*>(g_num)[i] = make_float4(0.f, 0.f, 0.f, 0.f);
}
__global__ void zero_den_kernel(int n) {
    int i = blockIdx.x * blockDim.x + threadIdx.x;
    if (i < n) g_denom[i] = 0.f;
}

// =====================================================================
// Fold all per-node scalar projections into U[32][128]:
//   col 0 : dW @ (fW[0:256]+fW[512:768])          -> p1
//   col 1 : dW @ (fW[256:512]-fW[512:768])        -> p2
//   col 2+c   (c=r*4+a) : wW[r][:,a*64:+64] @ aW[r][0:64]    -> qs
//   col 14+c  (c=r*4+a) : wW[r][:,a*64:+64] @ aW[r][64:128]  -> qd
//   cols 26..31 : zero
// =====================================================================
__global__ void prep_U_kernel(const float* __restrict__ dW, const float* __restrict__ fW,
                              const float* __restrict__ wW, const float* __restrict__ aW)
{
    int col = blockIdx.x;     // 0..31
    int k   = threadIdx.x;    // 0..127
    float s = 0.f;
    if (col < 2) {
        const float* dwr = dW + (size_t)k * HD;
        for (int j = 0; j < HD; j++) {
            float f = (col == 0) ? (fW[j] + fW[512 + j]) : (fW[256 + j] - fW[512 + j]);
            s += dwr[j] * f;
        }
    } else if (col < 26) {
        int c = col - 2;
        int half = 0;
        if (c >= 12) { c -= 12; half = 1; }
        int r = c >> 2, a = c & 3;
        const float* wwr = wW + ((size_t)r * KIN + k) * HD + a * 64;
        const float* awr = aW + r * 128 + half * 64;
        for (int j = 0; j < 64; j++) s += wwr[j] * awr[j];
    }
    g_U[col * KIN + k] = s;
}

__global__ void prep_Uc_kernel(const float* __restrict__ db, const float* __restrict__ fW,
                               const float* __restrict__ wb, const float* __restrict__ aW)
{
    int col = threadIdx.x;    // 0..31
    float s = 0.f;
    if (col < 2) {
        for (int j = 0; j < HD; j++) {
            float f = (col == 0) ? (fW[j] + fW[512 + j]) : (fW[256 + j] - fW[512 + j]);
            s += db[j] * f;
        }
    } else if (col < 26) {
        int c = col - 2;
        int half = 0;
        if (c >= 12) { c -= 12; half = 1; }
        int r = c >> 2, a = c & 3;
        const float* wbr = wb + r * HD + a * 64;
        const float* awr = aW + r * 128 + half * 64;
        for (int j = 0; j < 64; j++) s += wbr[j] * awr[j];
    }
    g_Uc[col] = s;
}

// =====================================================================
// Node scalars from h directly: one warp per node, lane = column.
//   scal[n, col] = h[n,:] . U[col,:] + Uc[col]
// =====================================================================
__global__ __launch_bounds__(256) void node_scalars_kernel(const float* __restrict__ h, int N)
{
    __shared__ float sh[8][KIN];
    const int tid  = threadIdx.x;
    const int node0 = blockIdx.x * 8;

    // stage 8 rows of h: 256 float4 loads
    {
        int row = tid >> 5;
        int w4  = tid & 31;
        int n = node0 + row;
        float4 v = make_float4(0.f, 0.f, 0.f, 0.f);
        if (n < N) v = *reinterpret_cast<const float4*>(h + (size_t)n * KIN + w4 * 4);
        *reinterpret_cast<float4*>(&sh[row][w4 * 4]) = v;
    }
    __syncthreads();

    const int w    = tid >> 5;
    const int lane = tid & 31;
    const int n    = node0 + w;
    if (n >= N || lane >= 26) return;

    const float4* urow = reinterpret_cast<const float4*>(g_U + lane * KIN);
    const float4* hrow = reinterpret_cast<const float4*>(&sh[w][0]);
    float acc = 0.f;
#pragma unroll
    for (int q = 0; q < 32; q++) {
        float4 hv = hrow[q];   // broadcast within warp
        float4 uv = urow[q];
        acc += hv.x * uv.x + hv.y * uv.y + hv.z * uv.z + hv.w * uv.w;
    }
    acc += g_Uc[lane];

    if (lane == 0)      g_p1[n] = acc;
    else if (lane == 1) g_p2[n] = acc;
    else if (lane < 14) {
        int c = lane - 2, r = c >> 2, a = c & 3;
        g_qs[((size_t)r * N + n) * 4 + a] = acc;
    } else {
        int c = lane - 14, r = c >> 2, a = c & 3;
        g_qd[((size_t)r * N + n) * 4 + a] = acc;
    }
}

// =====================================================================
// Tiled fp32 GEMM (R6 proven config): C = (scale ⊙ A) @ B + bias
// BM=128, BN=64, BK=16, TM=8, TN=4, 256 threads.
// SCALED: A row m, k-block (64-wide) scaled by rowScale[m*12 + (k>>6)].
// =====================================================================
#define GBM 128
#define GBN 64
#define GBK 16
template <bool SCALED>
__global__ __launch_bounds__(256) void gemm_bias_kernel(
    const float* __restrict__ A, const float* __restrict__ B,
    const float* __restrict__ bias, float* __restrict__ C,
    int M, int N, int K, const float* __restrict__ rowScale)
{
    __shared__ float As[GBK][GBM + 4];
    __shared__ float Bs[GBK][GBN];

    const int tid = threadIdx.x;
    const int tx = tid & 15;
    const int ty = tid >> 4;
    const int block_m = blockIdx.y * GBM;
    const int block_n = blockIdx.x * GBN;

    float acc[8][4];
#pragma unroll
    for (int i = 0; i < 8; i++)
#pragma unroll
        for (int j = 0; j < 4; j++) acc[i][j] = 0.f;

    const int b_row = tid >> 4;
    const int b_col = (tid & 15) << 2;

    for (int k0 = 0; k0 < K; k0 += GBK) {
#pragma unroll
        for (int f = tid; f < (GBM * GBK) / 4; f += 256) {
            int row = f >> 2;
            int kq  = (f & 3) << 2;
            int gm  = block_m + row;
            float4 av = make_float4(0.f, 0.f, 0.f, 0.f);
            if (gm < M) {
                av = *reinterpret_cast<const float4*>(A + (size_t)gm * K + k0 + kq);
                if (SCALED) {
                    float s = __ldg(rowScale + gm * 12 + ((k0 + kq) >> 6));
                    av.x *= s; av.y *= s; av.z *= s; av.w *= s;
                }
            }
            As[kq + 0][row] = av.x;
            As[kq + 1][row] = av.y;
            As[kq + 2][row] = av.z;
            As[kq + 3][row] = av.w;
        }
        {
            float4 bv = *reinterpret_cast<const float4*>(B + (size_t)(k0 + b_row) * N + block_n + b_col);
            *reinterpret_cast<float4*>(&Bs[b_row][b_col]) = bv;
        }
        __syncthreads();

#pragma unroll
        for (int k = 0; k < GBK; k++) {
            float4 ra0 = *reinterpret_cast<const float4*>(&As[k][ty * 8]);
            float4 ra1 = *reinterpret_cast<const float4*>(&As[k][ty * 8 + 4]);
            float4 rb  = *reinterpret_cast<const float4*>(&Bs[k][tx * 4]);
            float ra[8] = {ra0.x, ra0.y, ra0.z, ra0.w, ra1.x, ra1.y, ra1.z, ra1.w};
            float rbv[4] = {rb.x, rb.y, rb.z, rb.w};
#pragma unroll
            for (int i = 0; i < 8; i++)
#pragma unroll
                for (int j = 0; j < 4; j++)
                    acc[i][j] = fmaf(ra[i], rbv[j], acc[i][j]);
        }
        __syncthreads();
    }

    int n = block_n + tx * 4;
    float4 bb = *reinterpret_cast<const float4*>(bias + n);
#pragma unroll
    for (int i = 0; i < 8; i++) {
        int m = block_m + ty * 8 + i;
        if (m >= M) continue;
        float4 o;
        o.x = acc[i][0] + bb.x;
        o.y = acc[i][1] + bb.y;
        o.z = acc[i][2] + bb.z;
        o.w = acc[i][3] + bb.w;
        *reinterpret_cast<float4*>(C + (size_t)m * N + n) = o;
    }
}

// ---------------- edge kernel: one warp per edge ----------------
__global__ __launch_bounds__(256) void edge_kernel(
    const int* __restrict__ src, const int* __restrict__ dst,
    int r, const float* __restrict__ fb, const float* __restrict__ abr,
    int E, int N)
{
    int warp = (blockIdx.x * blockDim.x + threadIdx.x) >> 5;
    int lane = threadIdx.x & 31;
    if (warp >= E) return;

    const int s = __ldg(src + warp);
    const int d = __ldg(dst + warp);

    float score = g_p1[s] + g_p2[d] + fb[0];
    float sgn = (score > 0.f) ? 1.f : ((score < 0.f) ? -1.f : 0.f);

    const float* qsr = g_qs + (size_t)r * N * 4;
    const float* qdr = g_qd + (size_t)r * N * 4;
    int a = lane >> 3;
    float x = sgn * qsr[s * 4 + a] + qdr[d * 4 + a] + abr[0];
    float alpha = (x > 0.f) ? x : 0.01f * x;
    float ex = expf(alpha);

    if ((lane & 7) == 0)
        atomicAdd(g_denom + ((size_t)r * N + d) * 4 + a, ex);

    float v = ex * sgn;
    const float4* hrow = reinterpret_cast<const float4*>(g_hw + ((size_t)r * N + s) * HD) + lane * 2;
    float4 h0 = hrow[0];
    float4 h1 = hrow[1];
    float* out = g_num + (size_t)d * (RELS * HD) + r * HD + lane * 8;
    red_add_v4(out,     v * h0.x, v * h0.y, v * h0.z, v * h0.w);
    red_add_v4(out + 4, v * h1.x, v * h1.y, v * h1.z, v * h1.w);
}

// ---------------- reciprocal table: g_rcp[n*12 + r*4 + a] ----------------
__global__ void rcp_kernel(int N) {
    int i = blockIdx.x * blockDim.x + threadIdx.x;
    if (i >= N * 12) return;
    int n = i / 12;
    int c = i - n * 12;
    int r = c >> 2;
    int a = c & 3;
    float den = g_denom[((size_t)r * N + n) * 4 + a];
    g_rcp[i] = (den > 0.f) ? (1.f / den) : 0.f;
}

// ---------------- launch ----------------
extern "C" void kernel_launch(void* const* d_in, const int* in_sizes, int n_in,
                              void* d_out, int out_size)
{
    const float* h    = (const float*)d_in[0];
    const float* dW   = (const float*)d_in[1];
    const float* db   = (const float*)d_in[2];
    const float* fW   = (const float*)d_in[3];
    const float* fb   = (const float*)d_in[4];
    const float* wW   = (const float*)d_in[5];
    const float* wb   = (const float*)d_in[6];
    const float* aW   = (const float*)d_in[7];
    const float* ab   = (const float*)d_in[8];
    const float* linW = (const float*)d_in[9];
    const float* linb = (const float*)d_in[10];
    const int*   src  = (const int*)d_in[11];
    const int*   dst  = (const int*)d_in[12];

    const int N = in_sizes[0] / KIN;        // 50000
    const int E = in_sizes[11] / RELS;      // 300000

    float *p_hw, *p_num, *p_rcp;
    cudaGetSymbolAddress((void**)&p_hw,  g_hw);
    cudaGetSymbolAddress((void**)&p_num, g_num);
    cudaGetSymbolAddress((void**)&p_rcp, g_rcp);

    // zero accumulators
    {
        size_t n4 = (size_t)N * (RELS * HD) / 4;
        zero_num_kernel<<<(unsigned)((n4 + 255) / 256), 256>>>(n4);
        int nd = RELS * N * 4;
        zero_den_kernel<<<(nd + 255) / 256, 256>>>(nd);
    }

    // folded projection vectors + constants
    prep_U_kernel<<<32, 128>>>(dW, fW, wW, aW);
    prep_Uc_kernel<<<1, 32>>>(db, fW, wb, aW);

    // hw_r = h @ wW[r] + wb[r]   (the only remaining K=128 GEMMs)
    dim3 ggrid(HD / GBN, (N + GBM - 1) / GBM);   // (4, 391)
    for (int r = 0; r < RELS; r++)
        gemm_bias_kernel<false><<<ggrid, 256>>>(h, wW + (size_t)r * KIN * HD, wb + r * HD,
                                                p_hw + (size_t)r * N * HD, N, HD, KIN, nullptr);

    // per-node scalars straight from h
    node_scalars_kernel<<<(N + 7) / 8, 256>>>(h, N);

    // edge aggregation per relation
    for (int r = 0; r < RELS; r++)
        edge_kernel<<<(E + 7) / 8, 256>>>(src + (size_t)r * E, dst + (size_t)r * E,
                                          r, fb, ab + r, E, N);

    // reciprocal of softmax denominators (folded into final GEMM A-load)
    rcp_kernel<<<(N * 12 + 255) / 256, 256>>>(N);

    // out = (rcp ⊙ num) @ linW + linb
    gemm_bias_kernel<true><<<ggrid, 256>>>(p_num, linW, linb, (float*)d_out,
                                           N, HD, RELS * HD, p_rcp);
}

// round 10
// speedup vs baseline: 1.0618x; 1.0618x over previous
#include <cuda_runtime.h>
#include <cstdint>

#define RELS 3
#define NMAX 50000
#define HD   256      // H = HF*AH
#define KIN  128      // in_feats

// ---------------- scratch (static device globals; no allocation) ----------------
__device__ float g_hw   [(size_t)RELS * NMAX * HD];   // 153.6 MB
__device__ float g_num  [(size_t)NMAX * RELS * HD];   // 153.6 MB (concat layout [N, 768])
__device__ float g_denom[(size_t)RELS * NMAX * 4];    // [r][n][head]
__device__ float g_rcp  [(size_t)NMAX * 12];          // [n][r*4+a] reciprocal of denom
__device__ float g_p1   [NMAX];
__device__ float g_p2   [NMAX];
__device__ float g_qs   [(size_t)RELS * NMAX * 4];
__device__ float g_qd   [(size_t)RELS * NMAX * 4];
__device__ float g_U    [32 * KIN];                   // folded projection vectors [col][k]
__device__ float g_Uc   [32];                         // folded constants per col

// ---------------- helpers ----------------
__device__ __forceinline__ void red_add_v4(float* p, float x, float y, float z, float w) {
    asm volatile("red.global.add.v4.f32 [%0], {%1, %2, %3, %4};"
                 :: "l"(p), "f"(x), "f"(y), "f"(z), "f"(w) : "memory");
}
__device__ __forceinline__ unsigned long long pack2(float lo, float hi) {
    unsigned long long r;
    asm("mov.b64 %0, {%1, %2};" : "=l"(r) : "f"(lo), "f"(hi));
    return r;
}
__device__ __forceinline__ void unpack2(unsigned long long v, float& lo, float& hi) {
    asm("mov.b64 {%0, %1}, %2;" : "=f"(lo), "=f"(hi) : "l"(v));
}
// packed dual FMA: d = a * b + d (2x fp32 per issue slot; Blackwell FFMA2)
__device__ __forceinline__ void ffma2(unsigned long long& d,
                                      unsigned long long a, unsigned long long b) {
    asm("fma.rn.f32x2 %0, %1, %2, %0;" : "+l"(d) : "l"(a), "l"(b));
}

// ---------------- zero-init kernels ----------------
__global__ void zero_num_kernel(size_t n4) {
    size_t i = (size_t)blockIdx.x * blockDim.x + threadIdx.x;
    if (i < n4) reinterpret_cast<float4*>(g_num)[i] = make_float4(0.f, 0.f, 0.f, 0.f);
}
__global__ void zero_den_kernel(int n) {
    int i = blockIdx.x * blockDim.x + threadIdx.x;
    if (i < n) g_denom[i] = 0.f;
}

// =====================================================================
// Fold all per-node scalar projections into U[32][128]:
//   col 0 : dW @ (fW[0:256]+fW[512:768])          -> p1
//   col 1 : dW @ (fW[256:512]-fW[512:768])        -> p2
//   col 2+c   (c=r*4+a) : wW[r][:,a*64:+64] @ aW[r][0:64]    -> qs
//   col 14+c  (c=r*4+a) : wW[r][:,a*64:+64] @ aW[r][64:128]  -> qd
// =====================================================================
__global__ void prep_U_kernel(const float* __restrict__ dW, const float* __restrict__ fW,
                              const float* __restrict__ wW, const float* __restrict__ aW)
{
    int col = blockIdx.x;     // 0..31
    int k   = threadIdx.x;    // 0..127
    float s = 0.f;
    if (col < 2) {
        const float* dwr = dW + (size_t)k * HD;
        for (int j = 0; j < HD; j++) {
            float f = (col == 0) ? (fW[j] + fW[512 + j]) : (fW[256 + j] - fW[512 + j]);
            s += dwr[j] * f;
        }
    } else if (col < 26) {
        int c = col - 2;
        int half = 0;
        if (c >= 12) { c -= 12; half = 1; }
        int r = c >> 2, a = c & 3;
        const float* wwr = wW + ((size_t)r * KIN + k) * HD + a * 64;
        const float* awr = aW + r * 128 + half * 64;
        for (int j = 0; j < 64; j++) s += wwr[j] * awr[j];
    }
    g_U[col * KIN + k] = s;
}

// one warp per column, lanes reduce over j
__global__ void prep_Uc_kernel(const float* __restrict__ db, const float* __restrict__ fW,
                               const float* __restrict__ wb, const float* __restrict__ aW)
{
    int col  = threadIdx.x >> 5;   // 0..31 (blockDim = 1024)
    int lane = threadIdx.x & 31;
    float s = 0.f;
    if (col < 2) {
        for (int j = lane; j < HD; j += 32) {
            float f = (col == 0) ? (fW[j] + fW[512 + j]) : (fW[256 + j] - fW[512 + j]);
            s += db[j] * f;
        }
    } else if (col < 26) {
        int c = col - 2;
        int half = 0;
        if (c >= 12) { c -= 12; half = 1; }
        int r = c >> 2, a = c & 3;
        for (int j = lane; j < 64; j += 32)
            s += wb[r * HD + a * 64 + j] * aW[r * 128 + half * 64 + j];
    }
#pragma unroll
    for (int o = 16; o > 0; o >>= 1) s += __shfl_xor_sync(0xFFFFFFFFu, s, o);
    if (lane == 0) g_Uc[col] = s;
}

// =====================================================================
// Node scalars from h directly: one warp per node, lane = column.
// =====================================================================
__global__ __launch_bounds__(256) void node_scalars_kernel(const float* __restrict__ h, int N)
{
    __shared__ float sh[8][KIN];
    const int tid  = threadIdx.x;
    const int node0 = blockIdx.x * 8;

    {
        int row = tid >> 5;
        int w4  = tid & 31;
        int n = node0 + row;
        float4 v = make_float4(0.f, 0.f, 0.f, 0.f);
        if (n < N) v = *reinterpret_cast<const float4*>(h + (size_t)n * KIN + w4 * 4);
        *reinterpret_cast<float4*>(&sh[row][w4 * 4]) = v;
    }
    __syncthreads();

    const int w    = tid >> 5;
    const int lane = tid & 31;
    const int n    = node0 + w;
    if (n >= N || lane >= 26) return;

    const float4* urow = reinterpret_cast<const float4*>(g_U + lane * KIN);
    const float4* hrow = reinterpret_cast<const float4*>(&sh[w][0]);
    float acc = 0.f;
#pragma unroll
    for (int q = 0; q < 32; q++) {
        float4 hv = hrow[q];
        float4 uv = urow[q];
        acc += hv.x * uv.x + hv.y * uv.y + hv.z * uv.z + hv.w * uv.w;
    }
    acc += g_Uc[lane];

    if (lane == 0)      g_p1[n] = acc;
    else if (lane == 1) g_p2[n] = acc;
    else if (lane < 14) {
        int c = lane - 2, r = c >> 2, a = c & 3;
        g_qs[((size_t)r * N + n) * 4 + a] = acc;
    } else {
        int c = lane - 14, r = c >> 2, a = c & 3;
        g_qd[((size_t)r * N + n) * 4 + a] = acc;
    }
}

// =====================================================================
// Tiled fp32 GEMM with packed f32x2 FMA: C = (scale ⊙ A) @ B + bias
// BM=128, BN=64, BK=16, TM=8, TN=4 (as 2 packed col-pairs), 256 threads.
// SCALED: A row m, k-block (64-wide) scaled by rowScale[m*12 + (k>>6)].
// =====================================================================
#define GBM 128
#define GBN 64
#define GBK 16
template <bool SCALED>
__global__ __launch_bounds__(256) void gemm_bias_kernel(
    const float* __restrict__ A, const float* __restrict__ B,
    const float* __restrict__ bias, float* __restrict__ C,
    int M, int N, int K, const float* __restrict__ rowScale)
{
    __shared__ float As[GBK][GBM + 4];
    __shared__ float Bs[GBK][GBN];

    const int tid = threadIdx.x;
    const int tx = tid & 15;
    const int ty = tid >> 4;
    const int block_m = blockIdx.y * GBM;
    const int block_n = blockIdx.x * GBN;

    // accumulators: 8 rows x (2 packed f32x2 col-pairs) = 32 fp32
    unsigned long long acc2[8][2];
    const unsigned long long z2 = pack2(0.f, 0.f);
#pragma unroll
    for (int i = 0; i < 8; i++) { acc2[i][0] = z2; acc2[i][1] = z2; }

    const int b_row = tid >> 4;
    const int b_col = (tid & 15) << 2;

    for (int k0 = 0; k0 < K; k0 += GBK) {
#pragma unroll
        for (int f = tid; f < (GBM * GBK) / 4; f += 256) {
            int row = f >> 2;
            int kq  = (f & 3) << 2;
            int gm  = block_m + row;
            float4 av = make_float4(0.f, 0.f, 0.f, 0.f);
            if (gm < M) {
                av = *reinterpret_cast<const float4*>(A + (size_t)gm * K + k0 + kq);
                if (SCALED) {
                    float s = __ldg(rowScale + gm * 12 + ((k0 + kq) >> 6));
                    av.x *= s; av.y *= s; av.z *= s; av.w *= s;
                }
            }
            As[kq + 0][row] = av.x;
            As[kq + 1][row] = av.y;
            As[kq + 2][row] = av.z;
            As[kq + 3][row] = av.w;
        }
        {
            float4 bv = *reinterpret_cast<const float4*>(B + (size_t)(k0 + b_row) * N + block_n + b_col);
            *reinterpret_cast<float4*>(&Bs[b_row][b_col]) = bv;
        }
        __syncthreads();

#pragma unroll
        for (int k = 0; k < GBK; k++) {
            float4 ra0 = *reinterpret_cast<const float4*>(&As[k][ty * 8]);
            float4 ra1 = *reinterpret_cast<const float4*>(&As[k][ty * 8 + 4]);
            float4 rb  = *reinterpret_cast<const float4*>(&Bs[k][tx * 4]);
            unsigned long long b01 = pack2(rb.x, rb.y);
            unsigned long long b23 = pack2(rb.z, rb.w);
            float ra[8] = {ra0.x, ra0.y, ra0.z, ra0.w, ra1.x, ra1.y, ra1.z, ra1.w};
#pragma unroll
            for (int i = 0; i < 8; i++) {
                unsigned long long ad = pack2(ra[i], ra[i]);
                ffma2(acc2[i][0], ad, b01);
                ffma2(acc2[i][1], ad, b23);
            }
        }
        __syncthreads();
    }

    int n = block_n + tx * 4;
    float4 bb = *reinterpret_cast<const float4*>(bias + n);
#pragma unroll
    for (int i = 0; i < 8; i++) {
        int m = block_m + ty * 8 + i;
        if (m >= M) continue;
        float4 o;
        unpack2(acc2[i][0], o.x, o.y);
        unpack2(acc2[i][1], o.z, o.w);
        o.x += bb.x; o.y += bb.y; o.z += bb.z; o.w += bb.w;
        *reinterpret_cast<float4*>(C + (size_t)m * N + n) = o;
    }
}

// ---------------- edge kernel: one warp per edge ----------------
__global__ __launch_bounds__(256) void edge_kernel(
    const int* __restrict__ src, const int* __restrict__ dst,
    int r, const float* __restrict__ fb, const float* __restrict__ abr,
    int E, int N)
{
    int warp = (blockIdx.x * blockDim.x + threadIdx.x) >> 5;
    int lane = threadIdx.x & 31;
    if (warp >= E) return;

    const int s = __ldg(src + warp);
    const int d = __ldg(dst + warp);

    float score = g_p1[s] + g_p2[d] + fb[0];
    float sgn = (score > 0.f) ? 1.f : ((score < 0.f) ? -1.f : 0.f);

    const float* qsr = g_qs + (size_t)r * N * 4;
    const float* qdr = g_qd + (size_t)r * N * 4;
    int a = lane >> 3;
    float x = sgn * qsr[s * 4 + a] + qdr[d * 4 + a] + abr[0];
    float alpha = (x > 0.f) ? x : 0.01f * x;
    float ex = expf(alpha);

    if ((lane & 7) == 0)
        atomicAdd(g_denom + ((size_t)r * N + d) * 4 + a, ex);

    float v = ex * sgn;
    const float4* hrow = reinterpret_cast<const float4*>(g_hw + ((size_t)r * N + s) * HD) + lane * 2;
    float4 h0 = hrow[0];
    float4 h1 = hrow[1];
    float* out = g_num + (size_t)d * (RELS * HD) + r * HD + lane * 8;
    red_add_v4(out,     v * h0.x, v * h0.y, v * h0.z, v * h0.w);
    red_add_v4(out + 4, v * h1.x, v * h1.y, v * h1.z, v * h1.w);
}

// ---------------- reciprocal table: g_rcp[n*12 + r*4 + a] ----------------
__global__ void rcp_kernel(int N) {
    int i = blockIdx.x * blockDim.x + threadIdx.x;
    if (i >= N * 12) return;
    int n = i / 12;
    int c = i - n * 12;
    int r = c >> 2;
    int a = c & 3;
    float den = g_denom[((size_t)r * N + n) * 4 + a];
    g_rcp[i] = (den > 0.f) ? (1.f / den) : 0.f;
}

// ---------------- launch ----------------
extern "C" void kernel_launch(void* const* d_in, const int* in_sizes, int n_in,
                              void* d_out, int out_size)
{
    const float* h    = (const float*)d_in[0];
    const float* dW   = (const float*)d_in[1];
    const float* db   = (const float*)d_in[2];
    const float* fW   = (const float*)d_in[3];
    const float* fb   = (const float*)d_in[4];
    const float* wW   = (const float*)d_in[5];
    const float* wb   = (const float*)d_in[6];
    const float* aW   = (const float*)d_in[7];
    const float* ab   = (const float*)d_in[8];
    const float* linW = (const float*)d_in[9];
    const float* linb = (const float*)d_in[10];
    const int*   src  = (const int*)d_in[11];
    const int*   dst  = (const int*)d_in[12];

    const int N = in_sizes[0] / KIN;        // 50000
    const int E = in_sizes[11] / RELS;      // 300000

    float *p_hw, *p_num, *p_rcp;
    cudaGetSymbolAddress((void**)&p_hw,  g_hw);
    cudaGetSymbolAddress((void**)&p_num, g_num);
    cudaGetSymbolAddress((void**)&p_rcp, g_rcp);

    // zero accumulators
    {
        size_t n4 = (size_t)N * (RELS * HD) / 4;
        zero_num_kernel<<<(unsigned)((n4 + 255) / 256), 256>>>(n4);
        int nd = RELS * N * 4;
        zero_den_kernel<<<(nd + 255) / 256, 256>>>(nd);
    }

    // folded projection vectors + constants
    prep_U_kernel<<<32, 128>>>(dW, fW, wW, aW);
    prep_Uc_kernel<<<1, 1024>>>(db, fW, wb, aW);

    // hw_r = h @ wW[r] + wb[r]   (K=128 GEMMs)
    dim3 ggrid(HD / GBN, (N + GBM - 1) / GBM);   // (4, 391)
    for (int r = 0; r < RELS; r++)
        gemm_bias_kernel<false><<<ggrid, 256>>>(h, wW + (size_t)r * KIN * HD, wb + r * HD,
                                                p_hw + (size_t)r * N * HD, N, HD, KIN, nullptr);

    // per-node scalars straight from h
    node_scalars_kernel<<<(N + 7) / 8, 256>>>(h, N);

    // edge aggregation per relation
    for (int r = 0; r < RELS; r++)
        edge_kernel<<<(E + 7) / 8, 256>>>(src + (size_t)r * E, dst + (size_t)r * E,
                                          r, fb, ab + r, E, N);

    // reciprocal of softmax denominators (folded into final GEMM A-load)
    rcp_kernel<<<(N * 12 + 255) / 256, 256>>>(N);

    // out = (rcp ⊙ num) @ linW + linb
    gemm_bias_kernel<true><<<ggrid, 256>>>(p_num, linW, linb, (float*)d_out,
                                           N, HD, RELS * HD, p_rcp);
}

// round 11
// speedup vs baseline: 1.0812x; 1.0183x over previous
#include <cuda_runtime.h>
#include <cstdint>

#define RELS 3
#define NMAX 50000
#define HD   256      // H = HF*AH
#define KIN  128      // in_feats

typedef unsigned long long ull;

// ---------------- scratch (static device globals; no allocation) ----------------
__device__ float g_hw   [(size_t)RELS * NMAX * HD];   // 153.6 MB
__device__ float g_num  [(size_t)NMAX * RELS * HD];   // 153.6 MB (concat layout [N, 768])
__device__ float g_denom[(size_t)RELS * NMAX * 4];    // [r][n][head]
__device__ float g_rcp  [(size_t)NMAX * 12];          // [n][r*4+a] reciprocal of denom
__device__ float g_p1   [NMAX];
__device__ float g_p2   [NMAX];
__device__ float g_qs   [(size_t)RELS * NMAX * 4];
__device__ float g_qd   [(size_t)RELS * NMAX * 4];
__device__ float g_U    [32 * KIN];                   // folded projection vectors [col][k]
__device__ float g_Uc   [32];                         // folded constants per col

// ---------------- helpers ----------------
__device__ __forceinline__ void red_add_v4(float* p, float x, float y, float z, float w) {
    asm volatile("red.global.add.v4.f32 [%0], {%1, %2, %3, %4};"
                 :: "l"(p), "f"(x), "f"(y), "f"(z), "f"(w) : "memory");
}
__device__ __forceinline__ ull pack2(float lo, float hi) {
    ull r;
    asm("mov.b64 %0, {%1, %2};" : "=l"(r) : "f"(lo), "f"(hi));
    return r;
}
__device__ __forceinline__ void unpack2(ull v, float& lo, float& hi) {
    asm("mov.b64 {%0, %1}, %2;" : "=f"(lo), "=f"(hi) : "l"(v));
}
// packed dual FMA: d = a * b + d (2x fp32 per issue slot; Blackwell FFMA2)
__device__ __forceinline__ void ffma2(ull& d, ull a, ull b) {
    asm("fma.rn.f32x2 %0, %1, %2, %0;" : "+l"(d) : "l"(a), "l"(b));
}

// ---------------- zero-init kernels ----------------
__global__ void zero_num_kernel(size_t n4) {
    size_t i = (size_t)blockIdx.x * blockDim.x + threadIdx.x;
    if (i < n4) reinterpret_cast<float4*>(g_num)[i] = make_float4(0.f, 0.f, 0.f, 0.f);
}
__global__ void zero_den_kernel(int n) {
    int i = blockIdx.x * blockDim.x + threadIdx.x;
    if (i < n) g_denom[i] = 0.f;
}

// =====================================================================
// Fold all per-node scalar projections into U[32][128]:
//   col 0 : dW @ (fW[0:256]+fW[512:768])          -> p1
//   col 1 : dW @ (fW[256:512]-fW[512:768])        -> p2
//   col 2+c   (c=r*4+a) : wW[r][:,a*64:+64] @ aW[r][0:64]    -> qs
//   col 14+c  (c=r*4+a) : wW[r][:,a*64:+64] @ aW[r][64:128]  -> qd
// =====================================================================
__global__ void prep_U_kernel(const float* __restrict__ dW, const float* __restrict__ fW,
                              const float* __restrict__ wW, const float* __restrict__ aW)
{
    int col = blockIdx.x;     // 0..31
    int k   = threadIdx.x;    // 0..127
    float s = 0.f;
    if (col < 2) {
        const float* dwr = dW + (size_t)k * HD;
        for (int j = 0; j < HD; j++) {
            float f = (col == 0) ? (fW[j] + fW[512 + j]) : (fW[256 + j] - fW[512 + j]);
            s += dwr[j] * f;
        }
    } else if (col < 26) {
        int c = col - 2;
        int half = 0;
        if (c >= 12) { c -= 12; half = 1; }
        int r = c >> 2, a = c & 3;
        const float* wwr = wW + ((size_t)r * KIN + k) * HD + a * 64;
        const float* awr = aW + r * 128 + half * 64;
        for (int j = 0; j < 64; j++) s += wwr[j] * awr[j];
    }
    g_U[col * KIN + k] = s;
}

// one warp per column, lanes reduce over j
__global__ void prep_Uc_kernel(const float* __restrict__ db, const float* __restrict__ fW,
                               const float* __restrict__ wb, const float* __restrict__ aW)
{
    int col  = threadIdx.x >> 5;   // 0..31 (blockDim = 1024)
    int lane = threadIdx.x & 31;
    float s = 0.f;
    if (col < 2) {
        for (int j = lane; j < HD; j += 32) {
            float f = (col == 0) ? (fW[j] + fW[512 + j]) : (fW[256 + j] - fW[512 + j]);
            s += db[j] * f;
        }
    } else if (col < 26) {
        int c = col - 2;
        int half = 0;
        if (c >= 12) { c -= 12; half = 1; }
        int r = c >> 2, a = c & 3;
        for (int j = lane; j < 64; j += 32)
            s += wb[r * HD + a * 64 + j] * aW[r * 128 + half * 64 + j];
    }
#pragma unroll
    for (int o = 16; o > 0; o >>= 1) s += __shfl_xor_sync(0xFFFFFFFFu, s, o);
    if (lane == 0) g_Uc[col] = s;
}

// =====================================================================
// Node scalars from h directly: one warp per node, lane = column.
// =====================================================================
__global__ __launch_bounds__(256) void node_scalars_kernel(const float* __restrict__ h, int N)
{
    __shared__ float sh[8][KIN];
    const int tid  = threadIdx.x;
    const int node0 = blockIdx.x * 8;

    {
        int row = tid >> 5;
        int w4  = tid & 31;
        int n = node0 + row;
        float4 v = make_float4(0.f, 0.f, 0.f, 0.f);
        if (n < N) v = *reinterpret_cast<const float4*>(h + (size_t)n * KIN + w4 * 4);
        *reinterpret_cast<float4*>(&sh[row][w4 * 4]) = v;
    }
    __syncthreads();

    const int w    = tid >> 5;
    const int lane = tid & 31;
    const int n    = node0 + w;
    if (n >= N || lane >= 26) return;

    const float4* urow = reinterpret_cast<const float4*>(g_U + lane * KIN);
    const float4* hrow = reinterpret_cast<const float4*>(&sh[w][0]);
    float acc = 0.f;
#pragma unroll
    for (int q = 0; q < 32; q++) {
        float4 hv = hrow[q];
        float4 uv = urow[q];
        acc += hv.x * uv.x + hv.y * uv.y + hv.z * uv.z + hv.w * uv.w;
    }
    acc += g_Uc[lane];

    if (lane == 0)      g_p1[n] = acc;
    else if (lane == 1) g_p2[n] = acc;
    else if (lane < 14) {
        int c = lane - 2, r = c >> 2, a = c & 3;
        g_qs[((size_t)r * N + n) * 4 + a] = acc;
    } else {
        int c = lane - 14, r = c >> 2, a = c & 3;
        g_qd[((size_t)r * N + n) * 4 + a] = acc;
    }
}

// =====================================================================
// Tiled fp32 GEMM, FFMA2 + 8x8 microtile: C = (scale ⊙ A) @ B + bias
// BM=128, BN=64, BK=16, 128 threads (4 warps), single-buffered smem.
// Per k-step per thread: 4x LDS.128 feed 64 FLOP (32 FFMA2).
// blockIdx.z batches over B/bias/C with the given strides.
// SCALED: A row m, k-block (64-wide) scaled by rowScale[m*12 + (k>>6)].
// =====================================================================
#define GBM 128
#define GBN 64
#define GBK 16
template <bool SCALED>
__global__ __launch_bounds__(128, 4) void gemm_bias_kernel(
    const float* __restrict__ A, const float* __restrict__ B,
    const float* __restrict__ bias, float* __restrict__ C,
    int M, int N, int K, const float* __restrict__ rowScale,
    size_t bStride, size_t biasStride, size_t cStride)
{
    const int z = blockIdx.z;
    B    += (size_t)z * bStride;
    bias += (size_t)z * biasStride;
    C    += (size_t)z * cStride;

    __shared__ float As[GBK][GBM + 4];
    __shared__ float Bs[GBK][GBN];

    const int tid = threadIdx.x;
    const int tx  = tid & 7;          // col group: 8 cols each
    const int ty  = tid >> 3;         // row group: 0..15, 8 rows each
    const int block_m = blockIdx.y * GBM;
    const int block_n = blockIdx.x * GBN;

    // accumulators: 8 rows x 4 packed f32x2 col-pairs = 64 fp32-equiv... (8x8 fp32)
    ull acc2[8][4];
    const ull z2 = pack2(0.f, 0.f);
#pragma unroll
    for (int i = 0; i < 8; i++)
#pragma unroll
        for (int j = 0; j < 4; j++) acc2[i][j] = z2;

    const int b_row = tid >> 4;            // 0..7 (second half +8)
    const int b_col = (tid & 15) << 2;     // 0..60

    for (int k0 = 0; k0 < K; k0 += GBK) {
        // A tile: 128x16 = 512 float4, 4 per thread
#pragma unroll
        for (int i = 0; i < 4; i++) {
            int f   = tid + i * 128;
            int row = f >> 2;
            int kq  = (f & 3) << 2;
            int gm  = block_m + row;
            float4 av = make_float4(0.f, 0.f, 0.f, 0.f);
            if (gm < M) {
                av = *reinterpret_cast<const float4*>(A + (size_t)gm * K + k0 + kq);
                if (SCALED) {
                    float s = __ldg(rowScale + gm * 12 + ((k0 + kq) >> 6));
                    av.x *= s; av.y *= s; av.z *= s; av.w *= s;
                }
            }
            As[kq + 0][row] = av.x;
            As[kq + 1][row] = av.y;
            As[kq + 2][row] = av.z;
            As[kq + 3][row] = av.w;
        }
        // B tile: 16x64 = 256 float4, 2 per thread
        {
            float4 bv0 = *reinterpret_cast<const float4*>(B + (size_t)(k0 + b_row)     * N + block_n + b_col);
            float4 bv1 = *reinterpret_cast<const float4*>(B + (size_t)(k0 + b_row + 8) * N + block_n + b_col);
            *reinterpret_cast<float4*>(&Bs[b_row][b_col])     = bv0;
            *reinterpret_cast<float4*>(&Bs[b_row + 8][b_col]) = bv1;
        }
        __syncthreads();

#pragma unroll
        for (int k = 0; k < GBK; k++) {
            float4 a0 = *reinterpret_cast<const float4*>(&As[k][ty * 8]);
            float4 a1 = *reinterpret_cast<const float4*>(&As[k][ty * 8 + 4]);
            float4 b0 = *reinterpret_cast<const float4*>(&Bs[k][tx * 8]);
            float4 b1 = *reinterpret_cast<const float4*>(&Bs[k][tx * 8 + 4]);
            ull bp[4] = {pack2(b0.x, b0.y), pack2(b0.z, b0.w),
                         pack2(b1.x, b1.y), pack2(b1.z, b1.w)};
            float ra[8] = {a0.x, a0.y, a0.z, a0.w, a1.x, a1.y, a1.z, a1.w};
#pragma unroll
            for (int i = 0; i < 8; i++) {
                ull ad = pack2(ra[i], ra[i]);
                ffma2(acc2[i][0], ad, bp[0]);
                ffma2(acc2[i][1], ad, bp[1]);
                ffma2(acc2[i][2], ad, bp[2]);
                ffma2(acc2[i][3], ad, bp[3]);
            }
        }
        __syncthreads();
    }

    // epilogue: 8 rows x 8 cols
    const int n0 = block_n + tx * 8;
    float4 bb0 = *reinterpret_cast<const float4*>(bias + n0);
    float4 bb1 = *reinterpret_cast<const float4*>(bias + n0 + 4);
#pragma unroll
    for (int i = 0; i < 8; i++) {
        int m = block_m + ty * 8 + i;
        if (m >= M) continue;
        float4 o0, o1;
        unpack2(acc2[i][0], o0.x, o0.y);
        unpack2(acc2[i][1], o0.z, o0.w);
        unpack2(acc2[i][2], o1.x, o1.y);
        unpack2(acc2[i][3], o1.z, o1.w);
        o0.x += bb0.x; o0.y += bb0.y; o0.z += bb0.z; o0.w += bb0.w;
        o1.x += bb1.x; o1.y += bb1.y; o1.z += bb1.z; o1.w += bb1.w;
        *reinterpret_cast<float4*>(C + (size_t)m * N + n0)     = o0;
        *reinterpret_cast<float4*>(C + (size_t)m * N + n0 + 4) = o1;
    }
}

// ---------------- edge kernel: one warp per edge ----------------
__global__ __launch_bounds__(256) void edge_kernel(
    const int* __restrict__ src, const int* __restrict__ dst,
    int r, const float* __restrict__ fb, const float* __restrict__ abr,
    int E, int N)
{
    int warp = (blockIdx.x * blockDim.x + threadIdx.x) >> 5;
    int lane = threadIdx.x & 31;
    if (warp >= E) return;

    const int s = __ldg(src + warp);
    const int d = __ldg(dst + warp);

    float score = g_p1[s] + g_p2[d] + fb[0];
    float sgn = (score > 0.f) ? 1.f : ((score < 0.f) ? -1.f : 0.f);

    const float* qsr = g_qs + (size_t)r * N * 4;
    const float* qdr = g_qd + (size_t)r * N * 4;
    int a = lane >> 3;
    float x = sgn * qsr[s * 4 + a] + qdr[d * 4 + a] + abr[0];
    float alpha = (x > 0.f) ? x : 0.01f * x;
    float ex = expf(alpha);

    if ((lane & 7) == 0)
        atomicAdd(g_denom + ((size_t)r * N + d) * 4 + a, ex);

    float v = ex * sgn;
    const float4* hrow = reinterpret_cast<const float4*>(g_hw + ((size_t)r * N + s) * HD) + lane * 2;
    float4 h0 = hrow[0];
    float4 h1 = hrow[1];
    float* out = g_num + (size_t)d * (RELS * HD) + r * HD + lane * 8;
    red_add_v4(out,     v * h0.x, v * h0.y, v * h0.z, v * h0.w);
    red_add_v4(out + 4, v * h1.x, v * h1.y, v * h1.z, v * h1.w);
}

// ---------------- reciprocal table: g_rcp[n*12 + r*4 + a] ----------------
__global__ void rcp_kernel(int N) {
    int i = blockIdx.x * blockDim.x + threadIdx.x;
    if (i >= N * 12) return;
    int n = i / 12;
    int c = i - n * 12;
    int r = c >> 2;
    int a = c & 3;
    float den = g_denom[((size_t)r * N + n) * 4 + a];
    g_rcp[i] = (den > 0.f) ? (1.f / den) : 0.f;
}

// ---------------- launch ----------------
extern "C" void kernel_launch(void* const* d_in, const int* in_sizes, int n_in,
                              void* d_out, int out_size)
{
    const float* h    = (const float*)d_in[0];
    const float* dW   = (const float*)d_in[1];
    const float* db   = (const float*)d_in[2];
    const float* fW   = (const float*)d_in[3];
    const float* fb   = (const float*)d_in[4];
    const float* wW   = (const float*)d_in[5];
    const float* wb   = (const float*)d_in[6];
    const float* aW   = (const float*)d_in[7];
    const float* ab   = (const float*)d_in[8];
    const float* linW = (const float*)d_in[9];
    const float* linb = (const float*)d_in[10];
    const int*   src  = (const int*)d_in[11];
    const int*   dst  = (const int*)d_in[12];

    const int N = in_sizes[0] / KIN;        // 50000
    const int E = in_sizes[11] / RELS;      // 300000

    float *p_hw, *p_num, *p_rcp;
    cudaGetSymbolAddress((void**)&p_hw,  g_hw);
    cudaGetSymbolAddress((void**)&p_num, g_num);
    cudaGetSymbolAddress((void**)&p_rcp, g_rcp);

    // zero accumulators
    {
        size_t n4 = (size_t)N * (RELS * HD) / 4;
        zero_num_kernel<<<(unsigned)((n4 + 255) / 256), 256>>>(n4);
        int nd = RELS * N * 4;
        zero_den_kernel<<<(nd + 255) / 256, 256>>>(nd);
    }

    // folded projection vectors + constants
    prep_U_kernel<<<32, 128>>>(dW, fW, wW, aW);
    prep_Uc_kernel<<<1, 1024>>>(db, fW, wb, aW);

    // hw_r = h @ wW[r] + wb[r]  — batched over blockIdx.z
    {
        dim3 ggrid(HD / GBN, (N + GBM - 1) / GBM, RELS);   // (4, 391, 3)
        gemm_bias_kernel<false><<<ggrid, 128>>>(
            h, wW, wb, p_hw, N, HD, KIN, nullptr,
            (size_t)KIN * HD, (size_t)HD, (size_t)N * HD);
    }

    // per-node scalars straight from h
    node_scalars_kernel<<<(N + 7) / 8, 256>>>(h, N);

    // edge aggregation per relation
    for (int r = 0; r < RELS; r++)
        edge_kernel<<<(E + 7) / 8, 256>>>(src + (size_t)r * E, dst + (size_t)r * E,
                                          r, fb, ab + r, E, N);

    // reciprocal of softmax denominators (folded into final GEMM A-load)
    rcp_kernel<<<(N * 12 + 255) / 256, 256>>>(N);

    // out = (rcp ⊙ num) @ linW + linb
    {
        dim3 ggrid(HD / GBN, (N + GBM - 1) / GBM, 1);
        gemm_bias_kernel<true><<<ggrid, 128>>>(
            p_num, linW, linb, (float*)d_out, N, HD, RELS * HD, p_rcp, 0, 0, 0);
    }
}